// round 11
// baseline (speedup 1.0000x reference)
#include <cuda_runtime.h>
#include <cuda_bf16.h>
#include <math_constants.h>
#include <cstdint>

// ---------------- problem constants ----------------
#define BATCH 8
#define SEQ   2048
#define EMB   1024
#define HEAD  1024
#define MTOT  (BATCH * SEQ)
#define NQKV  (3 * HEAD)

// ---------------- mma.sync GEMM tiling ----------------
#define BM 128
#define BN 256
#define BK 64
#define NTHREADS 256
// SMEM row stride: 64 + 8 pad bf16 = 144 bytes (9*16B -> conflict-free ldmatrix)
#define ROWB 144
#define A_BYTES (128 * ROWB)            // 18432 per A array (hi or lo)
#define B_BYTES (256 * ROWB)            // 36864 per B array
#define OFF_AHI 0
#define OFF_ALO (A_BYTES)
#define OFF_BHI (2 * A_BYTES)
#define OFF_BLO (2 * A_BYTES + B_BYTES)
#define SMEM_DYN (128 * 257 * 4)        // 131584 epilogue fp32 buf; operands (110592) overlap

// ---------------- static scratch ----------------
__device__ __nv_bfloat16 g_Xhi[(size_t)MTOT * EMB];
__device__ __nv_bfloat16 g_Xlo[(size_t)MTOT * EMB];
__device__ __nv_bfloat16 g_Whi[(size_t)NQKV * EMB];
__device__ __nv_bfloat16 g_Wlo[(size_t)NQKV * EMB];
__device__ __nv_bfloat16 g_Qhi[(size_t)MTOT * HEAD];
__device__ __nv_bfloat16 g_Qlo[(size_t)MTOT * HEAD];
__device__ __nv_bfloat16 g_Khi[(size_t)MTOT * HEAD];
__device__ __nv_bfloat16 g_Klo[(size_t)MTOT * HEAD];
__device__ __nv_bfloat16 g_VThi[(size_t)BATCH * HEAD * SEQ];   // [b][h][t]
__device__ __nv_bfloat16 g_VTlo[(size_t)BATCH * HEAD * SEQ];
__device__ float         g_S[(size_t)BATCH * SEQ * SEQ];
__device__ __nv_bfloat16 g_Phi[(size_t)BATCH * SEQ * SEQ];
__device__ __nv_bfloat16 g_Plo[(size_t)BATCH * SEQ * SEQ];

// ---------------- helpers ----------------
__device__ __forceinline__ uint32_t smem_u32(const void* p) {
    uint32_t a;
    asm("{ .reg .u64 t; cvta.to.shared.u64 t, %1; cvt.u32.u64 %0, t; }" : "=r"(a) : "l"(p));
    return a;
}
#define CP_ASYNC16(dst, src) \
    asm volatile("cp.async.cg.shared.global [%0], [%1], 16;" :: "r"(dst), "l"(src))
#define CP_COMMIT() asm volatile("cp.async.commit_group;")
#define CP_WAIT0()  asm volatile("cp.async.wait_group 0;")

__device__ __forceinline__ void ldsm_x4(uint32_t& r0, uint32_t& r1, uint32_t& r2, uint32_t& r3,
                                        uint32_t addr) {
    asm volatile("ldmatrix.sync.aligned.m8n8.x4.shared.b16 {%0,%1,%2,%3}, [%4];"
                 : "=r"(r0), "=r"(r1), "=r"(r2), "=r"(r3) : "r"(addr));
}
__device__ __forceinline__ void mma_bf16(float* c, const uint32_t* a, uint32_t b0, uint32_t b1) {
    asm volatile("mma.sync.aligned.m16n8k16.row.col.f32.bf16.bf16.f32 "
                 "{%0,%1,%2,%3}, {%4,%5,%6,%7}, {%8,%9}, {%0,%1,%2,%3};"
                 : "+f"(c[0]), "+f"(c[1]), "+f"(c[2]), "+f"(c[3])
                 : "r"(a[0]), "r"(a[1]), "r"(a[2]), "r"(a[3]), "r"(b0), "r"(b1));
}

// ---------------------------------------------------------------------------
// split: fp32 -> (hi, lo) bf16.  which: 0 = x, 1..3 = Wq/Wk/Wv into stacked W
// ---------------------------------------------------------------------------
__global__ __launch_bounds__(256) void split_kernel(const float* __restrict__ src,
                                                    int which, int n4)
{
    int i = blockIdx.x * 256 + threadIdx.x;
    if (i >= n4) return;
    __nv_bfloat16 *hi, *lo;
    if (which == 0) { hi = g_Xhi; lo = g_Xlo; }
    else {
        size_t off = (size_t)(which - 1) * HEAD * EMB;
        hi = g_Whi + off; lo = g_Wlo + off;
    }
    float4 v = ((const float4*)src)[i];
    float f[4] = {v.x, v.y, v.z, v.w};
    ushort4 uh, ul;
    unsigned short* ph = &uh.x;
    unsigned short* pl = &ul.x;
#pragma unroll
    for (int j = 0; j < 4; j++) {
        __nv_bfloat16 h = __float2bfloat16(f[j]);
        __nv_bfloat16 l = __float2bfloat16(f[j] - __bfloat162float(h));
        ph[j] = __bfloat16_as_ushort(h);
        pl[j] = __bfloat16_as_ushort(l);
    }
    ((ushort4*)hi)[i] = uh;
    ((ushort4*)lo)[i] = ul;
}

// ---------------------------------------------------------------------------
// mma.sync bf16 3-pass GEMM, 128x256x64 CTA tile, 8 warps of 64x64.
// Single-buffered cp.async (proven R9 structure; warp tile widened).
// MODE 0: [16384,3072] = X * Wstack^T  -> Q/K hi/lo, V^T hi/lo
// MODE 1: S[b] = scale * Q K^T         (tile-level causal skip, 2*bx<=by live)
// MODE 2: O[b] = P * VT^T              (k-loop truncated at row tile ceiling)
// ---------------------------------------------------------------------------
template <int MODE>
__global__ __launch_bounds__(NTHREADS) void gemm_mma(float* __restrict__ outp)
{
    const int bx = blockIdx.x, by = blockIdx.y, bz = blockIdx.z;
    if (MODE == 1 && 2 * bx > by) return;      // tile fully above diagonal

    const int rowBase = by * BM;
    const int colBase = bx * BN;

    const __nv_bfloat16 *Ahi, *Alo, *Bhi, *Blo;
    int lda, ldb, kChunks;
    if (MODE == 0) {
        Ahi = g_Xhi; Alo = g_Xlo; Bhi = g_Whi; Blo = g_Wlo;
        lda = EMB; ldb = EMB; kChunks = EMB / BK;
    } else if (MODE == 1) {
        size_t o = (size_t)bz * SEQ * HEAD;
        Ahi = g_Qhi + o; Alo = g_Qlo + o; Bhi = g_Khi + o; Blo = g_Klo + o;
        lda = HEAD; ldb = HEAD; kChunks = HEAD / BK;
    } else {
        Ahi = g_Phi + (size_t)bz * SEQ * SEQ;   Alo = g_Plo + (size_t)bz * SEQ * SEQ;
        Bhi = g_VThi + (size_t)bz * HEAD * SEQ; Blo = g_VTlo + (size_t)bz * HEAD * SEQ;
        lda = SEQ; ldb = SEQ; kChunks = (rowBase + BM) / BK;
    }

    extern __shared__ char sm[];
    const uint32_t sbase = smem_u32(sm);

    const int tid  = threadIdx.x;
    const int lane = tid & 31;
    const int wid  = tid >> 5;
    const int wm   = wid >> 2;      // 0..1  (row 64-block)
    const int wn   = wid & 3;       // 0..3  (col 64-block)

    // ---- cp.async mapping: 6144 x 16B segs per chunk, 24 per thread ----
    const __nv_bfloat16* gA[2] = { Ahi + (size_t)rowBase * lda, Alo + (size_t)rowBase * lda };
    const __nv_bfloat16* gB[2] = { Bhi + (size_t)colBase * ldb, Blo + (size_t)colBase * ldb };

    // ---- ldmatrix addresses (per thread, fixed per kernel) ----
    const int aRow = wm * 64 + (lane & 15);                        // + mt*16
    const int aCol = (lane >> 4) * 8;
    const int bRow = wn * 64 + (lane & 7) + ((lane >> 4) << 3);    // + g*16
    const int bCol = ((lane >> 3) & 1) * 8;

    float acc[4][8][4];
#pragma unroll
    for (int mt = 0; mt < 4; mt++)
#pragma unroll
        for (int nt = 0; nt < 8; nt++)
#pragma unroll
            for (int i = 0; i < 4; i++) acc[mt][nt][i] = 0.f;

    // ------------------- K loop (single-buffered, BK=64) -------------------
    for (int ck = 0; ck < kChunks; ck++) {
        const int k0 = ck * BK;
        // A: 2 arrays x 128 rows x 8 segs = 2048 segs (8/thread)
#pragma unroll
        for (int i = 0; i < 8; i++) {
            const int t   = i * NTHREADS + tid;
            const int arr = t >> 10;
            const int rem = t & 1023;
            const int r   = rem >> 3;
            const int seg = rem & 7;
            CP_ASYNC16(sbase + OFF_AHI + arr * A_BYTES + r * ROWB + seg * 16,
                       gA[arr] + (size_t)r * lda + k0 + seg * 8);
        }
        // B: 2 arrays x 256 rows x 8 segs = 4096 segs (16/thread)
#pragma unroll
        for (int i = 0; i < 16; i++) {
            const int t   = i * NTHREADS + tid;
            const int arr = t >> 11;
            const int rem = t & 2047;
            const int r   = rem >> 3;
            const int seg = rem & 7;
            CP_ASYNC16(sbase + OFF_BHI + arr * B_BYTES + r * ROWB + seg * 16,
                       gB[arr] + (size_t)r * ldb + k0 + seg * 8);
        }
        CP_COMMIT();
        CP_WAIT0();
        __syncthreads();

#pragma unroll
        for (int ks = 0; ks < 4; ks++) {
            const int kc = ks * 16;
            uint32_t ah[4][4], al[4][4], bh[4][4], bl[4][4];
#pragma unroll
            for (int mt = 0; mt < 4; mt++) {
                const uint32_t ad = sbase + OFF_AHI +
                                    (aRow + mt * 16) * ROWB + (kc + aCol) * 2;
                ldsm_x4(ah[mt][0], ah[mt][1], ah[mt][2], ah[mt][3], ad);
            }
#pragma unroll
            for (int g = 0; g < 4; g++) {
                const uint32_t bd = sbase + OFF_BHI +
                                    (bRow + g * 16) * ROWB + (kc + bCol) * 2;
                ldsm_x4(bh[g][0], bh[g][1], bh[g][2], bh[g][3], bd);
            }
            // pass 1: Ahi * Bhi
#pragma unroll
            for (int mt = 0; mt < 4; mt++)
#pragma unroll
                for (int nt = 0; nt < 8; nt++)
                    mma_bf16(acc[mt][nt], ah[mt], bh[nt >> 1][(nt & 1) * 2],
                             bh[nt >> 1][(nt & 1) * 2 + 1]);
            // pass 2: Ahi * Blo
#pragma unroll
            for (int g = 0; g < 4; g++) {
                const uint32_t bd = sbase + OFF_BLO +
                                    (bRow + g * 16) * ROWB + (kc + bCol) * 2;
                ldsm_x4(bl[g][0], bl[g][1], bl[g][2], bl[g][3], bd);
            }
#pragma unroll
            for (int mt = 0; mt < 4; mt++)
#pragma unroll
                for (int nt = 0; nt < 8; nt++)
                    mma_bf16(acc[mt][nt], ah[mt], bl[nt >> 1][(nt & 1) * 2],
                             bl[nt >> 1][(nt & 1) * 2 + 1]);
            // pass 3: Alo * Bhi
#pragma unroll
            for (int mt = 0; mt < 4; mt++) {
                const uint32_t ad = sbase + OFF_ALO +
                                    (aRow + mt * 16) * ROWB + (kc + aCol) * 2;
                ldsm_x4(al[mt][0], al[mt][1], al[mt][2], al[mt][3], ad);
            }
#pragma unroll
            for (int mt = 0; mt < 4; mt++)
#pragma unroll
                for (int nt = 0; nt < 8; nt++)
                    mma_bf16(acc[mt][nt], al[mt], bh[nt >> 1][(nt & 1) * 2],
                             bh[nt >> 1][(nt & 1) * 2 + 1]);
        }
        __syncthreads();    // tile consumed; next chunk may overwrite
    }

    // ------------------- epilogue: stage to padded SMEM fp32 -------------------
    float* buf = (float*)sm;
    {
        const int rq = lane >> 2;
        const int cq = (lane & 3) * 2;
#pragma unroll
        for (int mt = 0; mt < 4; mt++)
#pragma unroll
            for (int nt = 0; nt < 8; nt++) {
                const int r = wm * 64 + mt * 16 + rq;
                const int c = wn * 64 + nt * 8 + cq;
                buf[r * 257 + c]           = acc[mt][nt][0];
                buf[r * 257 + c + 1]       = acc[mt][nt][1];
                buf[(r + 8) * 257 + c]     = acc[mt][nt][2];
                buf[(r + 8) * 257 + c + 1] = acc[mt][nt][3];
            }
    }
    __syncthreads();

    if (MODE == 0 && colBase >= 2 * HEAD) {
        // V segment -> transposed bf16 hi/lo: g_VT[b][h][t]; lanes sweep t (coalesced)
#pragma unroll 4
        for (int it = 0; it < 128; it++) {
            const int idx = it * NTHREADS + tid;
            const int hcol = idx >> 7, trow = idx & 127;
            const float v = buf[trow * 257 + hcol];
            const int m = rowBase + trow;
            const int b = m >> 11, tt = m & 2047;
            const int h = colBase - 2 * HEAD + hcol;
            const __nv_bfloat16 hi = __float2bfloat16(v);
            const __nv_bfloat16 lo = __float2bfloat16(v - __bfloat162float(hi));
            const size_t a = ((size_t)b * HEAD + h) * SEQ + tt;
            g_VThi[a] = hi; g_VTlo[a] = lo;
        }
    } else {
#pragma unroll 4
        for (int it = 0; it < 128; it++) {
            const int idx = it * NTHREADS + tid;
            const int row = idx >> 8, col = idx & 255;
            const float v = buf[row * 257 + col];
            const int m = rowBase + row;
            const int n = colBase + col;
            if (MODE == 0) {
                const __nv_bfloat16 hi = __float2bfloat16(v);
                const __nv_bfloat16 lo = __float2bfloat16(v - __bfloat162float(hi));
                if (n < HEAD) {
                    const size_t a = (size_t)m * HEAD + n;
                    g_Qhi[a] = hi; g_Qlo[a] = lo;
                } else {
                    const size_t a = (size_t)m * HEAD + (n - HEAD);
                    g_Khi[a] = hi; g_Klo[a] = lo;
                }
            } else if (MODE == 1) {
                g_S[((size_t)bz * SEQ + m) * SEQ + n] = v * 0.03125f;
            } else {
                outp[((size_t)bz * SEQ + m) * HEAD + n] = v;
            }
        }
    }
}

// ---------------------------------------------------------------------------
// causal softmax on g_S rows; writes P hi/lo bf16, zero-fill to 128-ceiling
// ---------------------------------------------------------------------------
__global__ __launch_bounds__(256) void softmax_kernel()
{
    const int t = blockIdx.x;
    const int b = blockIdx.y;
    const size_t off = ((size_t)b * SEQ + t) * SEQ;
    const float* __restrict__ row = g_S + off;
    const int L = t + 1;

    const int tid = threadIdx.x;
    const int lane = tid & 31;
    const int wid = tid >> 5;
    __shared__ float red[32];

    float lmax = -CUDART_INF_F;
    for (int i = tid; i < L; i += 256) lmax = fmaxf(lmax, row[i]);
#pragma unroll
    for (int o = 16; o > 0; o >>= 1) lmax = fmaxf(lmax, __shfl_xor_sync(0xffffffffu, lmax, o));
    if (lane == 0) red[wid] = lmax;
    __syncthreads();
    if (tid < 32) {
        float v = (tid < 8) ? red[tid] : -CUDART_INF_F;
#pragma unroll
        for (int o = 4; o > 0; o >>= 1) v = fmaxf(v, __shfl_xor_sync(0xffffffffu, v, o));
        if (tid == 0) red[0] = v;
    }
    __syncthreads();
    const float m = red[0];
    __syncthreads();

    float lsum = 0.f;
    for (int i = tid; i < L; i += 256) lsum += __expf(row[i] - m);
#pragma unroll
    for (int o = 16; o > 0; o >>= 1) lsum += __shfl_xor_sync(0xffffffffu, lsum, o);
    if (lane == 0) red[wid] = lsum;
    __syncthreads();
    if (tid < 32) {
        float v = (tid < 8) ? red[tid] : 0.f;
#pragma unroll
        for (int o = 4; o > 0; o >>= 1) v += __shfl_xor_sync(0xffffffffu, v, o);
        if (tid == 0) red[0] = v;
    }
    __syncthreads();
    const float inv = 1.f / red[0];

    for (int i = tid; i < L; i += 256) {
        const float p = __expf(row[i] - m) * inv;
        const __nv_bfloat16 hi = __float2bfloat16(p);
        const __nv_bfloat16 lo = __float2bfloat16(p - __bfloat162float(hi));
        g_Phi[off + i] = hi; g_Plo[off + i] = lo;
    }
    const int kCeil = ((t >> 7) + 1) << 7;     // PV reads only up to this tile edge
    const __nv_bfloat16 z = __float2bfloat16(0.f);
    for (int i = L + tid; i < kCeil; i += 256) { g_Phi[off + i] = z; g_Plo[off + i] = z; }
}

// ---------------------------------------------------------------------------
extern "C" void kernel_launch(void* const* d_in, const int* in_sizes, int n_in,
                              void* d_out, int out_size)
{
    const float* x  = (const float*)d_in[0];
    const float* Wq = (const float*)d_in[1];
    const float* Wk = (const float*)d_in[2];
    const float* Wv = (const float*)d_in[3];
    float* out = (float*)d_out;

    cudaFuncSetAttribute(gemm_mma<0>, cudaFuncAttributeMaxDynamicSharedMemorySize, SMEM_DYN);
    cudaFuncSetAttribute(gemm_mma<1>, cudaFuncAttributeMaxDynamicSharedMemorySize, SMEM_DYN);
    cudaFuncSetAttribute(gemm_mma<2>, cudaFuncAttributeMaxDynamicSharedMemorySize, SMEM_DYN);

    // 1. fp32 -> bf16 hi/lo splits
    const int nx4 = MTOT * EMB / 4;
    split_kernel<<<(nx4 + 255) / 256, 256>>>(x, 0, nx4);
    const int nw4 = HEAD * EMB / 4;
    split_kernel<<<(nw4 + 255) / 256, 256>>>(Wq, 1, nw4);
    split_kernel<<<(nw4 + 255) / 256, 256>>>(Wk, 2, nw4);
    split_kernel<<<(nw4 + 255) / 256, 256>>>(Wv, 3, nw4);

    // 2. QKV projection (tensor cores)
    dim3 g1(NQKV / BN, MTOT / BM);
    gemm_mma<0><<<g1, NTHREADS, SMEM_DYN>>>(nullptr);

    // 3. S = scale * Q K^T (causal tile skip)
    dim3 g2(SEQ / BN, SEQ / BM, BATCH);
    gemm_mma<1><<<g2, NTHREADS, SMEM_DYN>>>(nullptr);

    // 4. softmax -> P hi/lo
    dim3 g3(SEQ, BATCH);
    softmax_kernel<<<g3, 256>>>();

    // 5. O = P V
    dim3 g4(HEAD / BN, SEQ / BM, BATCH);
    gemm_mma<2><<<g4, NTHREADS, SMEM_DYN>>>(out);
}

// round 12
// speedup vs baseline: 1.0011x; 1.0011x over previous
#include <cuda_runtime.h>
#include <cuda_bf16.h>
#include <math_constants.h>
#include <cstdint>

// ---------------- problem constants ----------------
#define BATCH 8
#define SEQ   2048
#define EMB   1024
#define HEAD  1024
#define MTOT  (BATCH * SEQ)
#define NQKV  (3 * HEAD)

// ---------------- mma.sync GEMM tiling ----------------
#define BM 128
#define BN 128
#define BK 128
#define NTHREADS 256
// SMEM row stride: 128 + 8 pad bf16 = 272 bytes (17*16B -> conflict-free ldmatrix)
#define ROWB 272
#define ARR_BYTES (128 * ROWB)          // 34816 per operand array
#define SMEM_DYN (4 * ARR_BYTES)        // 139264; epilogue fp32 buf (66048) overlaps

// ---------------- static scratch ----------------
__device__ __nv_bfloat16 g_Xhi[(size_t)MTOT * EMB];
__device__ __nv_bfloat16 g_Xlo[(size_t)MTOT * EMB];
__device__ __nv_bfloat16 g_Whi[(size_t)NQKV * EMB];
__device__ __nv_bfloat16 g_Wlo[(size_t)NQKV * EMB];
__device__ __nv_bfloat16 g_Qhi[(size_t)MTOT * HEAD];
__device__ __nv_bfloat16 g_Qlo[(size_t)MTOT * HEAD];
__device__ __nv_bfloat16 g_Khi[(size_t)MTOT * HEAD];
__device__ __nv_bfloat16 g_Klo[(size_t)MTOT * HEAD];
__device__ __nv_bfloat16 g_VThi[(size_t)BATCH * HEAD * SEQ];   // [b][h][t]
__device__ __nv_bfloat16 g_VTlo[(size_t)BATCH * HEAD * SEQ];
__device__ float         g_S[(size_t)BATCH * SEQ * SEQ];
__device__ __nv_bfloat16 g_Phi[(size_t)BATCH * SEQ * SEQ];
__device__ __nv_bfloat16 g_Plo[(size_t)BATCH * SEQ * SEQ];

// ---------------- helpers ----------------
__device__ __forceinline__ uint32_t smem_u32(const void* p) {
    uint32_t a;
    asm("{ .reg .u64 t; cvta.to.shared.u64 t, %1; cvt.u32.u64 %0, t; }" : "=r"(a) : "l"(p));
    return a;
}
#define CP_ASYNC16(dst, src) \
    asm volatile("cp.async.cg.shared.global [%0], [%1], 16;" :: "r"(dst), "l"(src))
#define CP_COMMIT() asm volatile("cp.async.commit_group;")
#define CP_WAIT0()  asm volatile("cp.async.wait_group 0;")

__device__ __forceinline__ void ldsm_x4(uint32_t& r0, uint32_t& r1, uint32_t& r2, uint32_t& r3,
                                        uint32_t addr) {
    asm volatile("ldmatrix.sync.aligned.m8n8.x4.shared.b16 {%0,%1,%2,%3}, [%4];"
                 : "=r"(r0), "=r"(r1), "=r"(r2), "=r"(r3) : "r"(addr));
}
__device__ __forceinline__ void mma_bf16(float* c, const uint32_t* a, uint32_t b0, uint32_t b1) {
    asm volatile("mma.sync.aligned.m16n8k16.row.col.f32.bf16.bf16.f32 "
                 "{%0,%1,%2,%3}, {%4,%5,%6,%7}, {%8,%9}, {%0,%1,%2,%3};"
                 : "+f"(c[0]), "+f"(c[1]), "+f"(c[2]), "+f"(c[3])
                 : "r"(a[0]), "r"(a[1]), "r"(a[2]), "r"(a[3]), "r"(b0), "r"(b1));
}

// ---------------------------------------------------------------------------
// split: fp32 -> (hi, lo) bf16.  which: 0 = x, 1..3 = Wq/Wk/Wv into stacked W
// ---------------------------------------------------------------------------
__global__ __launch_bounds__(256) void split_kernel(const float* __restrict__ src,
                                                    int which, int n4)
{
    int i = blockIdx.x * 256 + threadIdx.x;
    if (i >= n4) return;
    __nv_bfloat16 *hi, *lo;
    if (which == 0) { hi = g_Xhi; lo = g_Xlo; }
    else {
        size_t off = (size_t)(which - 1) * HEAD * EMB;
        hi = g_Whi + off; lo = g_Wlo + off;
    }
    float4 v = ((const float4*)src)[i];
    float f[4] = {v.x, v.y, v.z, v.w};
    ushort4 uh, ul;
    unsigned short* ph = &uh.x;
    unsigned short* pl = &ul.x;
#pragma unroll
    for (int j = 0; j < 4; j++) {
        __nv_bfloat16 h = __float2bfloat16(f[j]);
        __nv_bfloat16 l = __float2bfloat16(f[j] - __bfloat162float(h));
        ph[j] = __bfloat16_as_ushort(h);
        pl[j] = __bfloat16_as_ushort(l);
    }
    ((ushort4*)hi)[i] = uh;
    ((ushort4*)lo)[i] = ul;
}

// ---------------------------------------------------------------------------
// mma.sync bf16 3-pass GEMM, 128x128x128 tile, NT, 256 threads (8 warps, 64x32
// warp tiles). Single-buffered cp.async (R9 structure, BK doubled to 128).
// MODE 0: [16384,3072] = X * Wstack^T  -> Q/K hi/lo, V^T hi/lo
// MODE 1: S[b] = scale * Q K^T         (tile-level causal skip)
// MODE 2: O[b] = P * VT^T              (k-loop truncated at row tile ceiling)
// ---------------------------------------------------------------------------
template <int MODE>
__global__ __launch_bounds__(NTHREADS) void gemm_mma(float* __restrict__ outp)
{
    const int bx = blockIdx.x, by = blockIdx.y, bz = blockIdx.z;
    if (MODE == 1 && bx > by) return;          // tile fully above diagonal

    const int rowBase = by * BM;
    const int colBase = bx * BN;

    const __nv_bfloat16 *Ahi, *Alo, *Bhi, *Blo;
    int lda, ldb, kChunks;
    if (MODE == 0) {
        Ahi = g_Xhi; Alo = g_Xlo; Bhi = g_Whi; Blo = g_Wlo;
        lda = EMB; ldb = EMB; kChunks = EMB / BK;
    } else if (MODE == 1) {
        size_t o = (size_t)bz * SEQ * HEAD;
        Ahi = g_Qhi + o; Alo = g_Qlo + o; Bhi = g_Khi + o; Blo = g_Klo + o;
        lda = HEAD; ldb = HEAD; kChunks = HEAD / BK;
    } else {
        Ahi = g_Phi + (size_t)bz * SEQ * SEQ;   Alo = g_Plo + (size_t)bz * SEQ * SEQ;
        Bhi = g_VThi + (size_t)bz * HEAD * SEQ; Blo = g_VTlo + (size_t)bz * HEAD * SEQ;
        lda = SEQ; ldb = SEQ; kChunks = (rowBase + BM) / BK;
    }

    extern __shared__ char sm[];
    const uint32_t sbase = smem_u32(sm);

    const int tid  = threadIdx.x;
    const int lane = tid & 31;
    const int wid  = tid >> 5;
    const int wm   = wid >> 2;      // 0..1
    const int wn   = wid & 3;       // 0..3

    // ---- cp.async mapping: 8192 x 16B segs per chunk, 32 per thread ----
    const __nv_bfloat16* abase[4] = {
        Ahi + (size_t)rowBase * lda, Alo + (size_t)rowBase * lda,
        Bhi + (size_t)colBase * ldb, Blo + (size_t)colBase * ldb };
    const int lds[4] = { lda, lda, ldb, ldb };

    // ---- ldmatrix addresses (per thread, fixed per kernel) ----
    const int aRow = wm * 64 + (lane & 15);
    const int aCol = (lane >> 4) * 8;
    const int bRow = wn * 32 + (lane & 7) + ((lane >> 4) << 3);
    const int bCol = ((lane >> 3) & 1) * 8;

    float acc[4][4][4];
#pragma unroll
    for (int mt = 0; mt < 4; mt++)
#pragma unroll
        for (int nt = 0; nt < 4; nt++)
#pragma unroll
            for (int i = 0; i < 4; i++) acc[mt][nt][i] = 0.f;

    // ------------------- K loop (single-buffered, BK=128) -------------------
    for (int ck = 0; ck < kChunks; ck++) {
        const int k0 = ck * BK;
#pragma unroll
        for (int i = 0; i < 32; i++) {
            const int t   = i * NTHREADS + tid;
            const int arr = t >> 11;            // 2048 segs per array
            const int rem = t & 2047;
            const int r   = rem >> 4;           // 16 segs per row
            const int seg = rem & 15;
            const __nv_bfloat16* src = abase[arr] + (size_t)r * lds[arr] + k0 + seg * 8;
            const uint32_t dst = sbase + arr * ARR_BYTES + r * ROWB + seg * 16;
            CP_ASYNC16(dst, src);
        }
        CP_COMMIT();
        CP_WAIT0();
        __syncthreads();

#pragma unroll
        for (int ks = 0; ks < 8; ks++) {
            const int kc = ks * 16;
            uint32_t ah[4][4], al[4][4], bh[2][4], bl[2][4];
#pragma unroll
            for (int mt = 0; mt < 4; mt++) {
                const uint32_t ad = sbase + 0 * ARR_BYTES +
                                    (aRow + mt * 16) * ROWB + (kc + aCol) * 2;
                ldsm_x4(ah[mt][0], ah[mt][1], ah[mt][2], ah[mt][3], ad);
            }
#pragma unroll
            for (int g = 0; g < 2; g++) {
                const uint32_t bd = sbase + 2 * ARR_BYTES +
                                    (bRow + g * 16) * ROWB + (kc + bCol) * 2;
                ldsm_x4(bh[g][0], bh[g][1], bh[g][2], bh[g][3], bd);
            }
            // pass 1: Ahi * Bhi
#pragma unroll
            for (int mt = 0; mt < 4; mt++)
#pragma unroll
                for (int nt = 0; nt < 4; nt++)
                    mma_bf16(acc[mt][nt], ah[mt], bh[nt >> 1][(nt & 1) * 2],
                             bh[nt >> 1][(nt & 1) * 2 + 1]);
            // pass 2: Ahi * Blo
#pragma unroll
            for (int g = 0; g < 2; g++) {
                const uint32_t bd = sbase + 3 * ARR_BYTES +
                                    (bRow + g * 16) * ROWB + (kc + bCol) * 2;
                ldsm_x4(bl[g][0], bl[g][1], bl[g][2], bl[g][3], bd);
            }
#pragma unroll
            for (int mt = 0; mt < 4; mt++)
#pragma unroll
                for (int nt = 0; nt < 4; nt++)
                    mma_bf16(acc[mt][nt], ah[mt], bl[nt >> 1][(nt & 1) * 2],
                             bl[nt >> 1][(nt & 1) * 2 + 1]);
            // pass 3: Alo * Bhi
#pragma unroll
            for (int mt = 0; mt < 4; mt++) {
                const uint32_t ad = sbase + 1 * ARR_BYTES +
                                    (aRow + mt * 16) * ROWB + (kc + aCol) * 2;
                ldsm_x4(al[mt][0], al[mt][1], al[mt][2], al[mt][3], ad);
            }
#pragma unroll
            for (int mt = 0; mt < 4; mt++)
#pragma unroll
                for (int nt = 0; nt < 4; nt++)
                    mma_bf16(acc[mt][nt], al[mt], bh[nt >> 1][(nt & 1) * 2],
                             bh[nt >> 1][(nt & 1) * 2 + 1]);
        }
        __syncthreads();    // tile consumed; next chunk may overwrite
    }

    // ------------------- epilogue: stage to padded SMEM fp32 -------------------
    float* buf = (float*)sm;
    {
        const int rq = lane >> 2;
        const int cq = (lane & 3) * 2;
#pragma unroll
        for (int mt = 0; mt < 4; mt++)
#pragma unroll
            for (int nt = 0; nt < 4; nt++) {
                const int r = wm * 64 + mt * 16 + rq;
                const int c = wn * 32 + nt * 8 + cq;
                buf[r * 129 + c]           = acc[mt][nt][0];
                buf[r * 129 + c + 1]       = acc[mt][nt][1];
                buf[(r + 8) * 129 + c]     = acc[mt][nt][2];
                buf[(r + 8) * 129 + c + 1] = acc[mt][nt][3];
            }
    }
    __syncthreads();

    if (MODE == 0 && colBase >= 2 * HEAD) {
        // V segment -> transposed bf16 hi/lo: g_VT[b][h][t]; lanes sweep t (coalesced)
#pragma unroll 4
        for (int it = 0; it < 64; it++) {
            const int idx = it * NTHREADS + tid;
            const int hcol = idx >> 7, trow = idx & 127;
            const float v = buf[trow * 129 + hcol];
            const int m = rowBase + trow;
            const int b = m >> 11, tt = m & 2047;
            const int h = colBase - 2 * HEAD + hcol;
            const __nv_bfloat16 hi = __float2bfloat16(v);
            const __nv_bfloat16 lo = __float2bfloat16(v - __bfloat162float(hi));
            const size_t a = ((size_t)b * HEAD + h) * SEQ + tt;
            g_VThi[a] = hi; g_VTlo[a] = lo;
        }
    } else {
#pragma unroll 4
        for (int it = 0; it < 64; it++) {
            const int idx = it * NTHREADS + tid;
            const int row = idx >> 7, col = idx & 127;
            const float v = buf[row * 129 + col];
            const int m = rowBase + row;
            const int n = colBase + col;
            if (MODE == 0) {
                const __nv_bfloat16 hi = __float2bfloat16(v);
                const __nv_bfloat16 lo = __float2bfloat16(v - __bfloat162float(hi));
                if (n < HEAD) {
                    const size_t a = (size_t)m * HEAD + n;
                    g_Qhi[a] = hi; g_Qlo[a] = lo;
                } else {
                    const size_t a = (size_t)m * HEAD + (n - HEAD);
                    g_Khi[a] = hi; g_Klo[a] = lo;
                }
            } else if (MODE == 1) {
                g_S[((size_t)bz * SEQ + m) * SEQ + n] = v * 0.03125f;
            } else {
                outp[((size_t)bz * SEQ + m) * HEAD + n] = v;
            }
        }
    }
}

// ---------------------------------------------------------------------------
// causal softmax on g_S rows; single-exp: pass 2 stores e into g_S, pass 3
// reads back and normalizes. Writes P hi/lo bf16, zero-fill to 128-ceiling.
// ---------------------------------------------------------------------------
__global__ __launch_bounds__(256) void softmax_kernel()
{
    const int t = blockIdx.x;
    const int b = blockIdx.y;
    const size_t off = ((size_t)b * SEQ + t) * SEQ;
    float* __restrict__ row = g_S + off;
    const int L = t + 1;

    const int tid = threadIdx.x;
    const int lane = tid & 31;
    const int wid = tid >> 5;
    __shared__ float red[32];

    float lmax = -CUDART_INF_F;
    for (int i = tid; i < L; i += 256) lmax = fmaxf(lmax, row[i]);
#pragma unroll
    for (int o = 16; o > 0; o >>= 1) lmax = fmaxf(lmax, __shfl_xor_sync(0xffffffffu, lmax, o));
    if (lane == 0) red[wid] = lmax;
    __syncthreads();
    if (tid < 32) {
        float v = (tid < 8) ? red[tid] : -CUDART_INF_F;
#pragma unroll
        for (int o = 4; o > 0; o >>= 1) v = fmaxf(v, __shfl_xor_sync(0xffffffffu, v, o));
        if (tid == 0) red[0] = v;
    }
    __syncthreads();
    const float m = red[0];
    __syncthreads();

    // exp once; stash e back into g_S
    float lsum = 0.f;
    for (int i = tid; i < L; i += 256) {
        const float e = __expf(row[i] - m);
        row[i] = e;
        lsum += e;
    }
#pragma unroll
    for (int o = 16; o > 0; o >>= 1) lsum += __shfl_xor_sync(0xffffffffu, lsum, o);
    if (lane == 0) red[wid] = lsum;
    __syncthreads();
    if (tid < 32) {
        float v = (tid < 8) ? red[tid] : 0.f;
#pragma unroll
        for (int o = 4; o > 0; o >>= 1) v += __shfl_xor_sync(0xffffffffu, v, o);
        if (tid == 0) red[0] = v;
    }
    __syncthreads();
    const float inv = 1.f / red[0];

    for (int i = tid; i < L; i += 256) {
        const float p = row[i] * inv;
        const __nv_bfloat16 hi = __float2bfloat16(p);
        const __nv_bfloat16 lo = __float2bfloat16(p - __bfloat162float(hi));
        g_Phi[off + i] = hi; g_Plo[off + i] = lo;
    }
    const int kCeil = ((t >> 7) + 1) << 7;     // PV reads only up to this tile edge
    const __nv_bfloat16 z = __float2bfloat16(0.f);
    for (int i = L + tid; i < kCeil; i += 256) { g_Phi[off + i] = z; g_Plo[off + i] = z; }
}

// ---------------------------------------------------------------------------
extern "C" void kernel_launch(void* const* d_in, const int* in_sizes, int n_in,
                              void* d_out, int out_size)
{
    const float* x  = (const float*)d_in[0];
    const float* Wq = (const float*)d_in[1];
    const float* Wk = (const float*)d_in[2];
    const float* Wv = (const float*)d_in[3];
    float* out = (float*)d_out;

    cudaFuncSetAttribute(gemm_mma<0>, cudaFuncAttributeMaxDynamicSharedMemorySize, SMEM_DYN);
    cudaFuncSetAttribute(gemm_mma<1>, cudaFuncAttributeMaxDynamicSharedMemorySize, SMEM_DYN);
    cudaFuncSetAttribute(gemm_mma<2>, cudaFuncAttributeMaxDynamicSharedMemorySize, SMEM_DYN);

    // 1. fp32 -> bf16 hi/lo splits
    const int nx4 = MTOT * EMB / 4;
    split_kernel<<<(nx4 + 255) / 256, 256>>>(x, 0, nx4);
    const int nw4 = HEAD * EMB / 4;
    split_kernel<<<(nw4 + 255) / 256, 256>>>(Wq, 1, nw4);
    split_kernel<<<(nw4 + 255) / 256, 256>>>(Wk, 2, nw4);
    split_kernel<<<(nw4 + 255) / 256, 256>>>(Wv, 3, nw4);

    // 2. QKV projection (tensor cores)
    dim3 g1(NQKV / BN, MTOT / BM);
    gemm_mma<0><<<g1, NTHREADS, SMEM_DYN>>>(nullptr);

    // 3. S = scale * Q K^T (causal tile skip)
    dim3 g2(SEQ / BN, SEQ / BM, BATCH);
    gemm_mma<1><<<g2, NTHREADS, SMEM_DYN>>>(nullptr);

    // 4. softmax -> P hi/lo (single exp)
    dim3 g3(SEQ, BATCH);
    softmax_kernel<<<g3, 256>>>();

    // 5. O = P V
    dim3 g4(HEAD / BN, SEQ / BM, BATCH);
    gemm_mma<2><<<g4, NTHREADS, SMEM_DYN>>>(out);
}

// round 13
// speedup vs baseline: 1.1645x; 1.1632x over previous
#include <cuda_runtime.h>
#include <cuda_bf16.h>
#include <math_constants.h>
#include <cstdint>

// ---------------- problem constants ----------------
#define BATCH 8
#define SEQ   2048
#define EMB   1024
#define HEAD  1024
#define MTOT  (BATCH * SEQ)
#define NQKV  (3 * HEAD)

// ---------------- mma.sync GEMM tiling ----------------
#define BM 128
#define BN 128
#define BK 64
#define NTHREADS 256
// SMEM row stride: 64 + 8 pad bf16 = 144 bytes (9*16B -> conflict-free ldmatrix)
#define ROWB 144
#define ARR_BYTES (128 * ROWB)          // 18432 per operand array
#define SMEM_DYN (4 * ARR_BYTES)        // 73728; epilogue fp32 buf (66048) overlaps

// ---------------- static scratch ----------------
__device__ __nv_bfloat16 g_Xhi[(size_t)MTOT * EMB];
__device__ __nv_bfloat16 g_Xlo[(size_t)MTOT * EMB];
__device__ __nv_bfloat16 g_Whi[(size_t)NQKV * EMB];
__device__ __nv_bfloat16 g_Wlo[(size_t)NQKV * EMB];
__device__ __nv_bfloat16 g_Qhi[(size_t)MTOT * HEAD];
__device__ __nv_bfloat16 g_Qlo[(size_t)MTOT * HEAD];
__device__ __nv_bfloat16 g_Khi[(size_t)MTOT * HEAD];
__device__ __nv_bfloat16 g_Klo[(size_t)MTOT * HEAD];
__device__ __nv_bfloat16 g_VThi[(size_t)BATCH * HEAD * SEQ];   // [b][h][t]
__device__ __nv_bfloat16 g_VTlo[(size_t)BATCH * HEAD * SEQ];
__device__ float         g_S[(size_t)BATCH * SEQ * SEQ];
__device__ __nv_bfloat16 g_Phi[(size_t)BATCH * SEQ * SEQ];
__device__ __nv_bfloat16 g_Plo[(size_t)BATCH * SEQ * SEQ];

// ---------------- helpers ----------------
__device__ __forceinline__ uint32_t smem_u32(const void* p) {
    uint32_t a;
    asm("{ .reg .u64 t; cvta.to.shared.u64 t, %1; cvt.u32.u64 %0, t; }" : "=r"(a) : "l"(p));
    return a;
}
#define CP_ASYNC16(dst, src) \
    asm volatile("cp.async.cg.shared.global [%0], [%1], 16;" :: "r"(dst), "l"(src))
#define CP_COMMIT() asm volatile("cp.async.commit_group;")
#define CP_WAIT0()  asm volatile("cp.async.wait_group 0;")

__device__ __forceinline__ void ldsm_x4(uint32_t& r0, uint32_t& r1, uint32_t& r2, uint32_t& r3,
                                        uint32_t addr) {
    asm volatile("ldmatrix.sync.aligned.m8n8.x4.shared.b16 {%0,%1,%2,%3}, [%4];"
                 : "=r"(r0), "=r"(r1), "=r"(r2), "=r"(r3) : "r"(addr));
}
__device__ __forceinline__ void mma_bf16(float* c, const uint32_t* a, uint32_t b0, uint32_t b1) {
    asm volatile("mma.sync.aligned.m16n8k16.row.col.f32.bf16.bf16.f32 "
                 "{%0,%1,%2,%3}, {%4,%5,%6,%7}, {%8,%9}, {%0,%1,%2,%3};"
                 : "+f"(c[0]), "+f"(c[1]), "+f"(c[2]), "+f"(c[3])
                 : "r"(a[0]), "r"(a[1]), "r"(a[2]), "r"(a[3]), "r"(b0), "r"(b1));
}

// ---------------------------------------------------------------------------
// split: fp32 -> (hi, lo) bf16.  which: 0 = x, 1..3 = Wq/Wk/Wv into stacked W
// ---------------------------------------------------------------------------
__global__ __launch_bounds__(256) void split_kernel(const float* __restrict__ src,
                                                    int which, int n4)
{
    int i = blockIdx.x * 256 + threadIdx.x;
    if (i >= n4) return;
    __nv_bfloat16 *hi, *lo;
    if (which == 0) { hi = g_Xhi; lo = g_Xlo; }
    else {
        size_t off = (size_t)(which - 1) * HEAD * EMB;
        hi = g_Whi + off; lo = g_Wlo + off;
    }
    float4 v = ((const float4*)src)[i];
    float f[4] = {v.x, v.y, v.z, v.w};
    ushort4 uh, ul;
    unsigned short* ph = &uh.x;
    unsigned short* pl = &ul.x;
#pragma unroll
    for (int j = 0; j < 4; j++) {
        __nv_bfloat16 h = __float2bfloat16(f[j]);
        __nv_bfloat16 l = __float2bfloat16(f[j] - __bfloat162float(h));
        ph[j] = __bfloat16_as_ushort(h);
        pl[j] = __bfloat16_as_ushort(l);
    }
    ((ushort4*)hi)[i] = uh;
    ((ushort4*)lo)[i] = ul;
}

// ---------------------------------------------------------------------------
// mma.sync bf16 3-pass GEMM, 128x128x64 tile, NT, 256 threads (8 warps, 64x32
// warp tiles). Single-buffered cp.async (exact R9 structure — best measured).
// MODE 0: [16384,3072] = X * Wstack^T  -> Q/K hi/lo, V^T hi/lo
// MODE 1: S[b] = scale * Q K^T         (tile-level causal skip)
// MODE 2: O[b] = P * VT^T              (k-loop truncated at row tile ceiling)
// ---------------------------------------------------------------------------
template <int MODE>
__global__ __launch_bounds__(NTHREADS) void gemm_mma(float* __restrict__ outp)
{
    const int bx = blockIdx.x, by = blockIdx.y, bz = blockIdx.z;
    if (MODE == 1 && bx > by) return;          // tile fully above diagonal

    const int rowBase = by * BM;
    const int colBase = bx * BN;

    const __nv_bfloat16 *Ahi, *Alo, *Bhi, *Blo;
    int lda, ldb, kChunks;
    if (MODE == 0) {
        Ahi = g_Xhi; Alo = g_Xlo; Bhi = g_Whi; Blo = g_Wlo;
        lda = EMB; ldb = EMB; kChunks = EMB / BK;
    } else if (MODE == 1) {
        size_t o = (size_t)bz * SEQ * HEAD;
        Ahi = g_Qhi + o; Alo = g_Qlo + o; Bhi = g_Khi + o; Blo = g_Klo + o;
        lda = HEAD; ldb = HEAD; kChunks = HEAD / BK;
    } else {
        Ahi = g_Phi + (size_t)bz * SEQ * SEQ;   Alo = g_Plo + (size_t)bz * SEQ * SEQ;
        Bhi = g_VThi + (size_t)bz * HEAD * SEQ; Blo = g_VTlo + (size_t)bz * HEAD * SEQ;
        lda = SEQ; ldb = SEQ; kChunks = (rowBase + BM) / BK;
    }

    extern __shared__ char sm[];
    const uint32_t sbase = smem_u32(sm);

    const int tid  = threadIdx.x;
    const int lane = tid & 31;
    const int wid  = tid >> 5;
    const int wm   = wid >> 2;      // 0..1
    const int wn   = wid & 3;       // 0..3

    // ---- cp.async mapping: 4096 x 16B segs per chunk, 16 per thread ----
    const __nv_bfloat16* abase[4] = {
        Ahi + (size_t)rowBase * lda, Alo + (size_t)rowBase * lda,
        Bhi + (size_t)colBase * ldb, Blo + (size_t)colBase * ldb };
    const int lds[4] = { lda, lda, ldb, ldb };

    // ---- ldmatrix addresses (per thread, fixed per kernel) ----
    const int aRow = wm * 64 + (lane & 15);
    const int aCol = (lane >> 4) * 8;
    const int bRow = wn * 32 + (lane & 7) + ((lane >> 4) << 3);
    const int bCol = ((lane >> 3) & 1) * 8;

    float acc[4][4][4];
#pragma unroll
    for (int mt = 0; mt < 4; mt++)
#pragma unroll
        for (int nt = 0; nt < 4; nt++)
#pragma unroll
            for (int i = 0; i < 4; i++) acc[mt][nt][i] = 0.f;

    // ------------------- K loop (single-buffered, BK=64) -------------------
    for (int ck = 0; ck < kChunks; ck++) {
        const int k0 = ck * BK;
#pragma unroll
        for (int i = 0; i < 16; i++) {
            const int t   = i * NTHREADS + tid;
            const int arr = t >> 10;
            const int rem = t & 1023;
            const int r   = rem >> 3;
            const int seg = rem & 7;
            const __nv_bfloat16* src = abase[arr] + (size_t)r * lds[arr] + k0 + seg * 8;
            const uint32_t dst = sbase + arr * ARR_BYTES + r * ROWB + seg * 16;
            CP_ASYNC16(dst, src);
        }
        CP_COMMIT();
        CP_WAIT0();
        __syncthreads();

#pragma unroll
        for (int ks = 0; ks < 4; ks++) {
            const int kc = ks * 16;
            uint32_t ah[4][4], al[4][4], bh[2][4], bl[2][4];
#pragma unroll
            for (int mt = 0; mt < 4; mt++) {
                const uint32_t ad = sbase + 0 * ARR_BYTES +
                                    (aRow + mt * 16) * ROWB + (kc + aCol) * 2;
                ldsm_x4(ah[mt][0], ah[mt][1], ah[mt][2], ah[mt][3], ad);
            }
#pragma unroll
            for (int g = 0; g < 2; g++) {
                const uint32_t bd = sbase + 2 * ARR_BYTES +
                                    (bRow + g * 16) * ROWB + (kc + bCol) * 2;
                ldsm_x4(bh[g][0], bh[g][1], bh[g][2], bh[g][3], bd);
            }
            // pass 1: Ahi * Bhi
#pragma unroll
            for (int mt = 0; mt < 4; mt++)
#pragma unroll
                for (int nt = 0; nt < 4; nt++)
                    mma_bf16(acc[mt][nt], ah[mt], bh[nt >> 1][(nt & 1) * 2],
                             bh[nt >> 1][(nt & 1) * 2 + 1]);
            // pass 2: Ahi * Blo
#pragma unroll
            for (int g = 0; g < 2; g++) {
                const uint32_t bd = sbase + 3 * ARR_BYTES +
                                    (bRow + g * 16) * ROWB + (kc + bCol) * 2;
                ldsm_x4(bl[g][0], bl[g][1], bl[g][2], bl[g][3], bd);
            }
#pragma unroll
            for (int mt = 0; mt < 4; mt++)
#pragma unroll
                for (int nt = 0; nt < 4; nt++)
                    mma_bf16(acc[mt][nt], ah[mt], bl[nt >> 1][(nt & 1) * 2],
                             bl[nt >> 1][(nt & 1) * 2 + 1]);
            // pass 3: Alo * Bhi
#pragma unroll
            for (int mt = 0; mt < 4; mt++) {
                const uint32_t ad = sbase + 1 * ARR_BYTES +
                                    (aRow + mt * 16) * ROWB + (kc + aCol) * 2;
                ldsm_x4(al[mt][0], al[mt][1], al[mt][2], al[mt][3], ad);
            }
#pragma unroll
            for (int mt = 0; mt < 4; mt++)
#pragma unroll
                for (int nt = 0; nt < 4; nt++)
                    mma_bf16(acc[mt][nt], al[mt], bh[nt >> 1][(nt & 1) * 2],
                             bh[nt >> 1][(nt & 1) * 2 + 1]);
        }
        __syncthreads();    // tile consumed; next chunk may overwrite
    }

    // ------------------- epilogue: stage to padded SMEM fp32 -------------------
    float* buf = (float*)sm;
    {
        const int rq = lane >> 2;
        const int cq = (lane & 3) * 2;
#pragma unroll
        for (int mt = 0; mt < 4; mt++)
#pragma unroll
            for (int nt = 0; nt < 4; nt++) {
                const int r = wm * 64 + mt * 16 + rq;
                const int c = wn * 32 + nt * 8 + cq;
                buf[r * 129 + c]           = acc[mt][nt][0];
                buf[r * 129 + c + 1]       = acc[mt][nt][1];
                buf[(r + 8) * 129 + c]     = acc[mt][nt][2];
                buf[(r + 8) * 129 + c + 1] = acc[mt][nt][3];
            }
    }
    __syncthreads();

    if (MODE == 0 && colBase >= 2 * HEAD) {
        // V segment -> transposed bf16 hi/lo: g_VT[b][h][t]; lanes sweep t (coalesced)
#pragma unroll 4
        for (int it = 0; it < 64; it++) {
            const int idx = it * NTHREADS + tid;
            const int hcol = idx >> 7, trow = idx & 127;
            const float v = buf[trow * 129 + hcol];
            const int m = rowBase + trow;
            const int b = m >> 11, tt = m & 2047;
            const int h = colBase - 2 * HEAD + hcol;
            const __nv_bfloat16 hi = __float2bfloat16(v);
            const __nv_bfloat16 lo = __float2bfloat16(v - __bfloat162float(hi));
            const size_t a = ((size_t)b * HEAD + h) * SEQ + tt;
            g_VThi[a] = hi; g_VTlo[a] = lo;
        }
    } else {
#pragma unroll 4
        for (int it = 0; it < 64; it++) {
            const int idx = it * NTHREADS + tid;
            const int row = idx >> 7, col = idx & 127;
            const float v = buf[row * 129 + col];
            const int m = rowBase + row;
            const int n = colBase + col;
            if (MODE == 0) {
                const __nv_bfloat16 hi = __float2bfloat16(v);
                const __nv_bfloat16 lo = __float2bfloat16(v - __bfloat162float(hi));
                if (n < HEAD) {
                    const size_t a = (size_t)m * HEAD + n;
                    g_Qhi[a] = hi; g_Qlo[a] = lo;
                } else {
                    const size_t a = (size_t)m * HEAD + (n - HEAD);
                    g_Khi[a] = hi; g_Klo[a] = lo;
                }
            } else if (MODE == 1) {
                g_S[((size_t)bz * SEQ + m) * SEQ + n] = v * 0.03125f;
            } else {
                outp[((size_t)bz * SEQ + m) * HEAD + n] = v;
            }
        }
    }
}

// ---------------------------------------------------------------------------
// causal softmax on g_S rows; single-exp: sum pass stores e into g_S, then
// normalize on read-back. Writes P hi/lo bf16, zero-fill to 128-ceiling.
// ---------------------------------------------------------------------------
__global__ __launch_bounds__(256) void softmax_kernel()
{
    const int t = blockIdx.x;
    const int b = blockIdx.y;
    const size_t off = ((size_t)b * SEQ + t) * SEQ;
    float* __restrict__ row = g_S + off;
    const int L = t + 1;

    const int tid = threadIdx.x;
    const int lane = tid & 31;
    const int wid = tid >> 5;
    __shared__ float red[32];

    float lmax = -CUDART_INF_F;
    for (int i = tid; i < L; i += 256) lmax = fmaxf(lmax, row[i]);
#pragma unroll
    for (int o = 16; o > 0; o >>= 1) lmax = fmaxf(lmax, __shfl_xor_sync(0xffffffffu, lmax, o));
    if (lane == 0) red[wid] = lmax;
    __syncthreads();
    if (tid < 32) {
        float v = (tid < 8) ? red[tid] : -CUDART_INF_F;
#pragma unroll
        for (int o = 4; o > 0; o >>= 1) v = fmaxf(v, __shfl_xor_sync(0xffffffffu, v, o));
        if (tid == 0) red[0] = v;
    }
    __syncthreads();
    const float m = red[0];
    __syncthreads();

    // exp once; stash e back into g_S
    float lsum = 0.f;
    for (int i = tid; i < L; i += 256) {
        const float e = __expf(row[i] - m);
        row[i] = e;
        lsum += e;
    }
#pragma unroll
    for (int o = 16; o > 0; o >>= 1) lsum += __shfl_xor_sync(0xffffffffu, lsum, o);
    if (lane == 0) red[wid] = lsum;
    __syncthreads();
    if (tid < 32) {
        float v = (tid < 8) ? red[tid] : 0.f;
#pragma unroll
        for (int o = 4; o > 0; o >>= 1) v += __shfl_xor_sync(0xffffffffu, v, o);
        if (tid == 0) red[0] = v;
    }
    __syncthreads();
    const float inv = 1.f / red[0];

    for (int i = tid; i < L; i += 256) {
        const float p = row[i] * inv;
        const __nv_bfloat16 hi = __float2bfloat16(p);
        const __nv_bfloat16 lo = __float2bfloat16(p - __bfloat162float(hi));
        g_Phi[off + i] = hi; g_Plo[off + i] = lo;
    }
    const int kCeil = ((t >> 7) + 1) << 7;     // PV reads only up to this tile edge
    const __nv_bfloat16 z = __float2bfloat16(0.f);
    for (int i = L + tid; i < kCeil; i += 256) { g_Phi[off + i] = z; g_Plo[off + i] = z; }
}

// ---------------------------------------------------------------------------
extern "C" void kernel_launch(void* const* d_in, const int* in_sizes, int n_in,
                              void* d_out, int out_size)
{
    const float* x  = (const float*)d_in[0];
    const float* Wq = (const float*)d_in[1];
    const float* Wk = (const float*)d_in[2];
    const float* Wv = (const float*)d_in[3];
    float* out = (float*)d_out;

    cudaFuncSetAttribute(gemm_mma<0>, cudaFuncAttributeMaxDynamicSharedMemorySize, SMEM_DYN);
    cudaFuncSetAttribute(gemm_mma<1>, cudaFuncAttributeMaxDynamicSharedMemorySize, SMEM_DYN);
    cudaFuncSetAttribute(gemm_mma<2>, cudaFuncAttributeMaxDynamicSharedMemorySize, SMEM_DYN);

    // 1. fp32 -> bf16 hi/lo splits
    const int nx4 = MTOT * EMB / 4;
    split_kernel<<<(nx4 + 255) / 256, 256>>>(x, 0, nx4);
    const int nw4 = HEAD * EMB / 4;
    split_kernel<<<(nw4 + 255) / 256, 256>>>(Wq, 1, nw4);
    split_kernel<<<(nw4 + 255) / 256, 256>>>(Wk, 2, nw4);
    split_kernel<<<(nw4 + 255) / 256, 256>>>(Wv, 3, nw4);

    // 2. QKV projection (tensor cores)
    dim3 g1(NQKV / BN, MTOT / BM);
    gemm_mma<0><<<g1, NTHREADS, SMEM_DYN>>>(nullptr);

    // 3. S = scale * Q K^T (causal tile skip)
    dim3 g2(SEQ / BN, SEQ / BM, BATCH);
    gemm_mma<1><<<g2, NTHREADS, SMEM_DYN>>>(nullptr);

    // 4. softmax -> P hi/lo (single exp)
    dim3 g3(SEQ, BATCH);
    softmax_kernel<<<g3, 256>>>();

    // 5. O = P V
    dim3 g4(HEAD / BN, SEQ / BM, BATCH);
    gemm_mma<2><<<g4, NTHREADS, SMEM_DYN>>>(out);
}

// round 14
// speedup vs baseline: 2.5043x; 2.1506x over previous
#include <cuda_runtime.h>
#include <cuda_fp16.h>
#include <math_constants.h>
#include <cstdint>

// ---------------- problem constants ----------------
#define BATCH 8
#define SEQ   2048
#define EMB   1024
#define HEAD  1024
#define MTOT  (BATCH * SEQ)
#define NQKV  (3 * HEAD)

// ---------------- mma.sync GEMM tiling ----------------
#define BM 128
#define BN 128
#define BK 64
#define NTHREADS 256
// SMEM row stride: 64 + 8 pad fp16 = 144 bytes (9*16B -> conflict-free ldmatrix)
#define ROWB 144
#define ARR_BYTES (128 * ROWB)          // 18432 per operand array (A, B)
#define SMEM_DYN (128 * 129 * 4)        // 66048 epilogue fp32 buf; operands (36864) overlap

// ---------------- static scratch (single fp16 arrays) ----------------
__device__ __half g_X[(size_t)MTOT * EMB];
__device__ __half g_W[(size_t)NQKV * EMB];
__device__ __half g_Q[(size_t)MTOT * HEAD];
__device__ __half g_K[(size_t)MTOT * HEAD];
__device__ __half g_VT[(size_t)BATCH * HEAD * SEQ];   // [b][h][t]
__device__ float  g_S[(size_t)BATCH * SEQ * SEQ];
__device__ __half g_P[(size_t)BATCH * SEQ * SEQ];

// ---------------- helpers ----------------
__device__ __forceinline__ uint32_t smem_u32(const void* p) {
    uint32_t a;
    asm("{ .reg .u64 t; cvta.to.shared.u64 t, %1; cvt.u32.u64 %0, t; }" : "=r"(a) : "l"(p));
    return a;
}
#define CP_ASYNC16(dst, src) \
    asm volatile("cp.async.cg.shared.global [%0], [%1], 16;" :: "r"(dst), "l"(src))
#define CP_COMMIT() asm volatile("cp.async.commit_group;")
#define CP_WAIT0()  asm volatile("cp.async.wait_group 0;")

__device__ __forceinline__ void ldsm_x4(uint32_t& r0, uint32_t& r1, uint32_t& r2, uint32_t& r3,
                                        uint32_t addr) {
    asm volatile("ldmatrix.sync.aligned.m8n8.x4.shared.b16 {%0,%1,%2,%3}, [%4];"
                 : "=r"(r0), "=r"(r1), "=r"(r2), "=r"(r3) : "r"(addr));
}
__device__ __forceinline__ void mma_f16(float* c, const uint32_t* a, uint32_t b0, uint32_t b1) {
    asm volatile("mma.sync.aligned.m16n8k16.row.col.f32.f16.f16.f32 "
                 "{%0,%1,%2,%3}, {%4,%5,%6,%7}, {%8,%9}, {%0,%1,%2,%3};"
                 : "+f"(c[0]), "+f"(c[1]), "+f"(c[2]), "+f"(c[3])
                 : "r"(a[0]), "r"(a[1]), "r"(a[2]), "r"(a[3]), "r"(b0), "r"(b1));
}

// ---------------------------------------------------------------------------
// convert: fp32 -> fp16.  which: 0 = x, 1..3 = Wq/Wk/Wv into stacked W
// ---------------------------------------------------------------------------
__global__ __launch_bounds__(256) void convert_kernel(const float* __restrict__ src,
                                                      int which, int n4)
{
    int i = blockIdx.x * 256 + threadIdx.x;
    if (i >= n4) return;
    __half* dst = (which == 0) ? g_X : g_W + (size_t)(which - 1) * HEAD * EMB;
    float4 v = ((const float4*)src)[i];
    ushort4 u;
    u.x = __half_as_ushort(__float2half(v.x));
    u.y = __half_as_ushort(__float2half(v.y));
    u.z = __half_as_ushort(__float2half(v.z));
    u.w = __half_as_ushort(__float2half(v.w));
    ((ushort4*)dst)[i] = u;
}

// ---------------------------------------------------------------------------
// mma.sync fp16 single-pass GEMM, 128x128x64 tile, NT, 256 threads (8 warps,
// 64x32 warp tiles). Single-buffered cp.async (R9 skeleton).
// MODE 0: [16384,3072] = X * Wstack^T  -> Q, K, V^T (fp16)
// MODE 1: S[b] = scale * Q K^T         (tile-level causal skip)
// MODE 2: O[b] = P * VT^T              (k-loop truncated at row tile ceiling)
// ---------------------------------------------------------------------------
template <int MODE>
__global__ __launch_bounds__(NTHREADS) void gemm_mma(float* __restrict__ outp)
{
    const int bx = blockIdx.x, by = blockIdx.y, bz = blockIdx.z;
    if (MODE == 1 && bx > by) return;          // tile fully above diagonal

    const int rowBase = by * BM;
    const int colBase = bx * BN;

    const __half *A, *B;
    int lda, ldb, kChunks;
    if (MODE == 0) {
        A = g_X; B = g_W;
        lda = EMB; ldb = EMB; kChunks = EMB / BK;
    } else if (MODE == 1) {
        size_t o = (size_t)bz * SEQ * HEAD;
        A = g_Q + o; B = g_K + o;
        lda = HEAD; ldb = HEAD; kChunks = HEAD / BK;
    } else {
        A = g_P + (size_t)bz * SEQ * SEQ;
        B = g_VT + (size_t)bz * HEAD * SEQ;
        lda = SEQ; ldb = SEQ; kChunks = (rowBase + BM) / BK;
    }

    extern __shared__ char sm[];
    const uint32_t sbase = smem_u32(sm);

    const int tid  = threadIdx.x;
    const int lane = tid & 31;
    const int wid  = tid >> 5;
    const int wm   = wid >> 2;      // 0..1
    const int wn   = wid & 3;       // 0..3

    // ---- cp.async mapping: 2048 x 16B segs per chunk, 8 per thread ----
    const __half* abase[2] = { A + (size_t)rowBase * lda, B + (size_t)colBase * ldb };
    const int lds[2] = { lda, ldb };

    // ---- ldmatrix addresses ----
    const int aRow = wm * 64 + (lane & 15);
    const int aCol = (lane >> 4) * 8;
    const int bRow = wn * 32 + (lane & 7) + ((lane >> 4) << 3);
    const int bCol = ((lane >> 3) & 1) * 8;

    float acc[4][4][4];
#pragma unroll
    for (int mt = 0; mt < 4; mt++)
#pragma unroll
        for (int nt = 0; nt < 4; nt++)
#pragma unroll
            for (int i = 0; i < 4; i++) acc[mt][nt][i] = 0.f;

    // ------------------- K loop (single-buffered, BK=64) -------------------
    for (int ck = 0; ck < kChunks; ck++) {
        const int k0 = ck * BK;
#pragma unroll
        for (int i = 0; i < 8; i++) {
            const int t   = i * NTHREADS + tid;
            const int arr = t >> 10;
            const int rem = t & 1023;
            const int r   = rem >> 3;
            const int seg = rem & 7;
            const __half* src = abase[arr] + (size_t)r * lds[arr] + k0 + seg * 8;
            const uint32_t dst = sbase + arr * ARR_BYTES + r * ROWB + seg * 16;
            CP_ASYNC16(dst, src);
        }
        CP_COMMIT();
        CP_WAIT0();
        __syncthreads();

#pragma unroll
        for (int ks = 0; ks < 4; ks++) {
            const int kc = ks * 16;
            uint32_t a[4][4], b[2][4];
#pragma unroll
            for (int mt = 0; mt < 4; mt++) {
                const uint32_t ad = sbase + 0 * ARR_BYTES +
                                    (aRow + mt * 16) * ROWB + (kc + aCol) * 2;
                ldsm_x4(a[mt][0], a[mt][1], a[mt][2], a[mt][3], ad);
            }
#pragma unroll
            for (int g = 0; g < 2; g++) {
                const uint32_t bd = sbase + 1 * ARR_BYTES +
                                    (bRow + g * 16) * ROWB + (kc + bCol) * 2;
                ldsm_x4(b[g][0], b[g][1], b[g][2], b[g][3], bd);
            }
#pragma unroll
            for (int mt = 0; mt < 4; mt++)
#pragma unroll
                for (int nt = 0; nt < 4; nt++)
                    mma_f16(acc[mt][nt], a[mt], b[nt >> 1][(nt & 1) * 2],
                            b[nt >> 1][(nt & 1) * 2 + 1]);
        }
        __syncthreads();    // tile consumed; next chunk may overwrite
    }

    // ------------------- epilogue: stage to padded SMEM fp32 -------------------
    float* buf = (float*)sm;
    {
        const int rq = lane >> 2;
        const int cq = (lane & 3) * 2;
#pragma unroll
        for (int mt = 0; mt < 4; mt++)
#pragma unroll
            for (int nt = 0; nt < 4; nt++) {
                const int r = wm * 64 + mt * 16 + rq;
                const int c = wn * 32 + nt * 8 + cq;
                buf[r * 129 + c]           = acc[mt][nt][0];
                buf[r * 129 + c + 1]       = acc[mt][nt][1];
                buf[(r + 8) * 129 + c]     = acc[mt][nt][2];
                buf[(r + 8) * 129 + c + 1] = acc[mt][nt][3];
            }
    }
    __syncthreads();

    if (MODE == 0 && colBase >= 2 * HEAD) {
        // V segment -> transposed fp16: g_VT[b][h][t]; lanes sweep t (coalesced)
#pragma unroll 4
        for (int it = 0; it < 64; it++) {
            const int idx = it * NTHREADS + tid;
            const int hcol = idx >> 7, trow = idx & 127;
            const float v = buf[trow * 129 + hcol];
            const int m = rowBase + trow;
            const int b = m >> 11, tt = m & 2047;
            const int h = colBase - 2 * HEAD + hcol;
            g_VT[((size_t)b * HEAD + h) * SEQ + tt] = __float2half(v);
        }
    } else {
#pragma unroll 4
        for (int it = 0; it < 64; it++) {
            const int idx = it * NTHREADS + tid;
            const int row = idx >> 7, col = idx & 127;
            const float v = buf[row * 129 + col];
            const int m = rowBase + row;
            const int n = colBase + col;
            if (MODE == 0) {
                if (n < HEAD) g_Q[(size_t)m * HEAD + n] = __float2half(v);
                else          g_K[(size_t)m * HEAD + (n - HEAD)] = __float2half(v);
            } else if (MODE == 1) {
                g_S[((size_t)bz * SEQ + m) * SEQ + n] = v * 0.03125f;
            } else {
                outp[((size_t)bz * SEQ + m) * HEAD + n] = v;
            }
        }
    }
}

// ---------------------------------------------------------------------------
// causal softmax on g_S rows; single-exp (stash e in g_S, normalize on
// read-back). Writes P fp16, zero-fill to 128-ceiling.
// ---------------------------------------------------------------------------
__global__ __launch_bounds__(256) void softmax_kernel()
{
    const int t = blockIdx.x;
    const int b = blockIdx.y;
    const size_t off = ((size_t)b * SEQ + t) * SEQ;
    float* __restrict__ row = g_S + off;
    const int L = t + 1;

    const int tid = threadIdx.x;
    const int lane = tid & 31;
    const int wid = tid >> 5;
    __shared__ float red[32];

    float lmax = -CUDART_INF_F;
    for (int i = tid; i < L; i += 256) lmax = fmaxf(lmax, row[i]);
#pragma unroll
    for (int o = 16; o > 0; o >>= 1) lmax = fmaxf(lmax, __shfl_xor_sync(0xffffffffu, lmax, o));
    if (lane == 0) red[wid] = lmax;
    __syncthreads();
    if (tid < 32) {
        float v = (tid < 8) ? red[tid] : -CUDART_INF_F;
#pragma unroll
        for (int o = 4; o > 0; o >>= 1) v = fmaxf(v, __shfl_xor_sync(0xffffffffu, v, o));
        if (tid == 0) red[0] = v;
    }
    __syncthreads();
    const float m = red[0];
    __syncthreads();

    float lsum = 0.f;
    for (int i = tid; i < L; i += 256) {
        const float e = __expf(row[i] - m);
        row[i] = e;
        lsum += e;
    }
#pragma unroll
    for (int o = 16; o > 0; o >>= 1) lsum += __shfl_xor_sync(0xffffffffu, lsum, o);
    if (lane == 0) red[wid] = lsum;
    __syncthreads();
    if (tid < 32) {
        float v = (tid < 8) ? red[tid] : 0.f;
#pragma unroll
        for (int o = 4; o > 0; o >>= 1) v += __shfl_xor_sync(0xffffffffu, v, o);
        if (tid == 0) red[0] = v;
    }
    __syncthreads();
    const float inv = 1.f / red[0];

    for (int i = tid; i < L; i += 256) g_P[off + i] = __float2half(row[i] * inv);
    const int kCeil = ((t >> 7) + 1) << 7;     // PV reads only up to this tile edge
    const __half z = __float2half(0.f);
    for (int i = L + tid; i < kCeil; i += 256) g_P[off + i] = z;
}

// ---------------------------------------------------------------------------
extern "C" void kernel_launch(void* const* d_in, const int* in_sizes, int n_in,
                              void* d_out, int out_size)
{
    const float* x  = (const float*)d_in[0];
    const float* Wq = (const float*)d_in[1];
    const float* Wk = (const float*)d_in[2];
    const float* Wv = (const float*)d_in[3];
    float* out = (float*)d_out;

    cudaFuncSetAttribute(gemm_mma<0>, cudaFuncAttributeMaxDynamicSharedMemorySize, SMEM_DYN);
    cudaFuncSetAttribute(gemm_mma<1>, cudaFuncAttributeMaxDynamicSharedMemorySize, SMEM_DYN);
    cudaFuncSetAttribute(gemm_mma<2>, cudaFuncAttributeMaxDynamicSharedMemorySize, SMEM_DYN);

    // 1. fp32 -> fp16 conversions
    const int nx4 = MTOT * EMB / 4;
    convert_kernel<<<(nx4 + 255) / 256, 256>>>(x, 0, nx4);
    const int nw4 = HEAD * EMB / 4;
    convert_kernel<<<(nw4 + 255) / 256, 256>>>(Wq, 1, nw4);
    convert_kernel<<<(nw4 + 255) / 256, 256>>>(Wk, 2, nw4);
    convert_kernel<<<(nw4 + 255) / 256, 256>>>(Wv, 3, nw4);

    // 2. QKV projection (tensor cores)
    dim3 g1(NQKV / BN, MTOT / BM);
    gemm_mma<0><<<g1, NTHREADS, SMEM_DYN>>>(nullptr);

    // 3. S = scale * Q K^T (causal tile skip)
    dim3 g2(SEQ / BN, SEQ / BM, BATCH);
    gemm_mma<1><<<g2, NTHREADS, SMEM_DYN>>>(nullptr);

    // 4. softmax -> P fp16 (single exp)
    dim3 g3(SEQ, BATCH);
    softmax_kernel<<<g3, 256>>>();

    // 5. O = P V
    dim3 g4(HEAD / BN, SEQ / BM, BATCH);
    gemm_mma<2><<<g4, NTHREADS, SMEM_DYN>>>(out);
}